// round 17
// baseline (speedup 1.0000x reference)
#include <cuda_runtime.h>
#include <cuda_fp16.h>
#include <cstdint>
#include <math.h>

// ---------------- problem constants ----------------
#define L_TOT   13294          // 10000 + 2500 + 625 + 169
#define BATCH   4
#define MROWS   (BATCH * L_TOT)   // 53176
#define DMODEL  256
#define DFFN    1024
#define NLAYERS_C 6
#define NHEADS  8

// weight layout offsets (elements) within one layer block
#define OFF_VP    0
#define OFF_SOAW  65536          // combined so(256) + aw(128) rows => [384,256]
#define OFF_OP    163840
#define OFF_F1    229376
#define OFF_F2    491520
#define LW_STRIDE 753664

// ---------------- device scratch (static, allowed) ----------------
__device__ __align__(16) float g_src  [MROWS * DMODEL];
__device__ __align__(16) float g_pos  [MROWS * DMODEL];
__device__ __align__(16) float g_offaw[MROWS * 384];

__device__ __align__(16) __half g_tmp_h [MROWS * DMODEL];
__device__ __align__(16) __half g_val_h [MROWS * DMODEL];
__device__ __align__(16) __half g_src_h [MROWS * DMODEL];
__device__ __align__(16) __half g_q_h   [MROWS * DMODEL];
__device__ __align__(16) __half g_attn_h[MROWS * DMODEL];
__device__ __align__(16) __half g_h_h   [(size_t)MROWS * DFFN];
__device__ __align__(16) __half g_w     [NLAYERS_C * LW_STRIDE];

// ---------------- helpers ----------------
__device__ __forceinline__ uint32_t smem_u32(const void* p) {
    uint32_t a;
    asm("{ .reg .u64 t; cvta.to.shared.u64 t, %1; cvt.u32.u64 %0, t; }" : "=r"(a) : "l"(p));
    return a;
}

#define LDMX4(r, addr) \
    asm volatile("ldmatrix.sync.aligned.m8n8.x4.shared.b16 {%0,%1,%2,%3}, [%4];" \
        : "=r"((r)[0]), "=r"((r)[1]), "=r"((r)[2]), "=r"((r)[3]) : "r"(addr))

__device__ __forceinline__ void mma16816(float* c, const uint32_t* a, const uint32_t* b) {
    asm volatile(
        "mma.sync.aligned.m16n8k16.row.col.f32.f16.f16.f32 "
        "{%0,%1,%2,%3}, {%4,%5,%6,%7}, {%8,%9}, {%0,%1,%2,%3};\n"
        : "+f"(c[0]), "+f"(c[1]), "+f"(c[2]), "+f"(c[3])
        : "r"(a[0]), "r"(a[1]), "r"(a[2]), "r"(a[3]), "r"(b[0]), "r"(b[1]));
}

#define CP_ASYNC16(dst, src, sz) \
    asm volatile("cp.async.cg.shared.global [%0], [%1], 16, %2;" \
        :: "r"(dst), "l"(src), "r"(sz))
#define CP_COMMIT() asm volatile("cp.async.commit_group;" ::: "memory")
#define CP_WAIT0()  asm volatile("cp.async.wait_group 0;" ::: "memory")

// ---------------- GEMM body: CTA 256x128, BK=64, 512 thr, 2-stage cp.async ----------
// 16 warps: wm = warp&7 (8 x 32 rows), wn = warp>>3 (2 x 64 cols).
// Warp microkernel 32x64 (2 m16 x 8 n8) — identical to proven version.
__device__ __forceinline__ void gemm_body(
    const __half* __restrict__ A, const __half* __restrict__ B,
    const float* __restrict__ bias, const float* __restrict__ bias2, int bias_split,
    float* __restrict__ Cf, __half* __restrict__ Ch,
    int Mr, int K, int N, int relu, int outmode, int row0, int col0, char* smem)
{
    const int ASZ = 256 * 144;         // 36864 B
    const int BSZ = 128 * 144;         // 18432 B
    const int STG = ASZ + BSZ;         // 55296 B per stage

    const int tid  = threadIdx.x;
    const int lane = tid & 31;
    const int warp = tid >> 5;          // 0..15
    const int wm   = warp & 7;          // 0..7 (32 rows each)
    const int wn   = warp >> 3;         // 0..1 (64 cols each)

    const uint32_t smem_base = smem_u32(smem);

    const int rowb = tid >> 3;            // 0..63
    const int seg  = tid & 7;             // 16B segment

    float acc[2][8][4];
    #pragma unroll
    for (int i = 0; i < 2; i++)
        #pragma unroll
        for (int j = 0; j < 8; j++)
            #pragma unroll
            for (int k = 0; k < 4; k++) acc[i][j][k] = 0.f;

    const int nch = K >> 6;

    auto load_chunk = [&](int ch, int stage) {
        const int kb = ch << 6;
        const uint32_t sb = smem_base + stage * STG;
        // A: 256 rows (rowb + r*64, r<4)
        #pragma unroll
        for (int r = 0; r < 4; r++) {
            const int rr = rowb + r * 64;
            const int ok = (row0 + rr < Mr) ? 16 : 0;
            const size_t gg = (size_t)(row0 + rr) * K + kb + seg * 8;
            CP_ASYNC16(sb + rr * 144 + seg * 16, A + gg, ok);
        }
        // B: 128 rows (rowb + r*64, r<2)
        #pragma unroll
        for (int r = 0; r < 2; r++) {
            const int rr = rowb + r * 64;
            const size_t gg = (size_t)(col0 + rr) * K + kb + seg * 8;
            CP_ASYNC16(sb + ASZ + rr * 144 + seg * 16, B + gg, 16);
        }
    };

    load_chunk(0, 0);
    CP_COMMIT();

    int stage = 0;
    for (int ch = 0; ch < nch; ch++) {
        CP_WAIT0();
        __syncthreads();
        if (ch + 1 < nch) {
            load_chunk(ch + 1, stage ^ 1);
            CP_COMMIT();
        }
        const uint32_t sb = smem_base + stage * STG;

        #pragma unroll
        for (int ks = 0; ks < 4; ks++) {
            const int k0 = ks << 4;
            uint32_t af[2][4];
            #pragma unroll
            for (int mt = 0; mt < 2; mt++) {
                const int arow = wm * 32 + mt * 16 + (lane & 15);
                const int acol = k0 + ((lane >> 4) << 3);
                LDMX4(af[mt], sb + arow * 144 + acol * 2);
            }
            #pragma unroll
            for (int np = 0; np < 4; np++) {
                const int tr = wn * 64 + np * 16 + ((lane >> 4) << 3) + (lane & 7);
                const int tc = k0 + (((lane >> 3) & 1) << 3);
                uint32_t t[4];
                LDMX4(t, sb + ASZ + tr * 144 + tc * 2);
                uint32_t b0[2] = { t[0], t[1] };
                uint32_t b1[2] = { t[2], t[3] };
                #pragma unroll
                for (int mt = 0; mt < 2; mt++) {
                    mma16816(acc[mt][np * 2 + 0], af[mt], b0);
                    mma16816(acc[mt][np * 2 + 1], af[mt], b1);
                }
            }
        }
        stage ^= 1;
    }

    // epilogue
    const int g  = lane >> 2;
    const int tg = lane & 3;
    #pragma unroll
    for (int mt = 0; mt < 2; mt++) {
        #pragma unroll
        for (int nt = 0; nt < 8; nt++) {
            const int col = col0 + wn * 64 + nt * 8 + tg * 2;
            float b0, b1;
            if (col < bias_split) {
                b0 = __ldg(bias + col);
                b1 = __ldg(bias + col + 1);
            } else {
                b0 = __ldg(bias2 + col - bias_split);
                b1 = __ldg(bias2 + col - bias_split + 1);
            }
            #pragma unroll
            for (int half_i = 0; half_i < 2; half_i++) {
                const int row = row0 + wm * 32 + mt * 16 + g + half_i * 8;
                if (row < Mr) {
                    float v0 = acc[mt][nt][half_i * 2 + 0] + b0;
                    float v1 = acc[mt][nt][half_i * 2 + 1] + b1;
                    if (relu) { v0 = fmaxf(v0, 0.f); v1 = fmaxf(v1, 0.f); }
                    if (outmode == 0) {
                        *reinterpret_cast<float2*>(Cf + (size_t)row * N + col) = make_float2(v0, v1);
                    } else {
                        *reinterpret_cast<__half2*>(Ch + (size_t)row * N + col) =
                            __halves2half2(__float2half(v0), __float2half(v1));
                    }
                }
            }
        }
    }
}

template<bool RELU, int OUTMODE>
__global__ __launch_bounds__(512, 1)
void mma_gemm(const __half* __restrict__ A, const __half* __restrict__ B,
              const float* __restrict__ bias, const float* __restrict__ bias2, int bias_split,
              float* __restrict__ Cf, __half* __restrict__ Ch,
              int Mr, int K, int N)
{
    extern __shared__ char smem[];
    gemm_body(A, B, bias, bias2, bias_split, Cf, Ch, Mr, K, N,
              RELU ? 1 : 0, OUTMODE, blockIdx.x * 256, blockIdx.y * 128, smem);
}

// Dual GEMM: y < ysplit -> GEMM1 (fp16 out), else GEMM2 (fp32 out, split bias).
__global__ __launch_bounds__(512, 1)
void dual_gemm(const __half* __restrict__ A1, const __half* __restrict__ B1,
               const float* __restrict__ bias1, __half* __restrict__ Ch1, int N1, int ysplit,
               const __half* __restrict__ A2, const __half* __restrict__ B2,
               const float* __restrict__ bias2a, const float* __restrict__ bias2b,
               float* __restrict__ Cf2, int N2,
               int Mr, int K)
{
    extern __shared__ char smem[];
    const int y = blockIdx.y;
    if (y < ysplit) {
        gemm_body(A1, B1, bias1, bias1, N1, nullptr, Ch1, Mr, K, N1,
                  0, 1, blockIdx.x * 256, y * 128, smem);
    } else {
        gemm_body(A2, B2, bias2a, bias2b, 256, Cf2, nullptr, Mr, K, N2,
                  0, 0, blockIdx.x * 256, (y - ysplit) * 128, smem);
    }
}

// ---------------- weight prep: ALL weight types + layers, one launch ----------------
__global__ void wprep_all_kernel(const float* __restrict__ vp, const float* __restrict__ so,
                                 const float* __restrict__ aw, const float* __restrict__ op,
                                 const float* __restrict__ f1, const float* __restrict__ f2,
                                 __half* __restrict__ dst)
{
    int idx = blockIdx.x * blockDim.x + threadIdx.x;
    if (idx >= NLAYERS_C * LW_STRIDE) return;
    int l = idx / LW_STRIDE;
    int r = idx - l * LW_STRIDE;
    const float* W;
    int K, N, r0;
    if (r < 131072) {
        if (r < 65536) { W = vp; K = 256; N = 256; r0 = r; }
        else           { W = so; K = 256; N = 256; r0 = r - 65536; }
    } else if (r < 229376) {
        if (r < 163840) { W = aw; K = 256; N = 128; r0 = r - 131072; }
        else            { W = op; K = 256; N = 256; r0 = r - 163840; }
    } else {
        if (r < 491520) { W = f1; K = 256;  N = 1024; r0 = r - 229376; }
        else            { W = f2; K = 1024; N = 256;  r0 = r - 491520; }
    }
    int n = r0 / K, k = r0 - n * K;
    dst[idx] = __float2half(__ldg(W + (size_t)l * K * N + (size_t)k * N + n));
}

// ---------------- flatten: (B,D,H,W) -> (B,L,D); emits src fp16 + q fp16 -----------
__global__ void flatten_kernel(const float* __restrict__ s0, const float* __restrict__ s1,
                               const float* __restrict__ s2, const float* __restrict__ s3,
                               const float* __restrict__ p0, const float* __restrict__ p1,
                               const float* __restrict__ p2, const float* __restrict__ p3,
                               const float* __restrict__ lvl_emb)
{
    long long idx = (long long)blockIdx.x * blockDim.x + threadIdx.x;
    const long long tot = (long long)MROWS * DMODEL;
    if (idx >= tot) return;
    int d = (int)(idx & 255);
    int m = (int)(idx >> 8);
    int b = m / L_TOT;
    int n = m - b * L_TOT;
    int lvl, hw, HW;
    const float *sp, *pp;
    if (n < 10000)      { lvl = 0; hw = n;         HW = 10000; sp = s0; pp = p0; }
    else if (n < 12500) { lvl = 1; hw = n - 10000; HW = 2500;  sp = s1; pp = p1; }
    else if (n < 13125) { lvl = 2; hw = n - 12500; HW = 625;   sp = s2; pp = p2; }
    else                { lvl = 3; hw = n - 13125; HW = 169;   sp = s3; pp = p3; }
    size_t sidx = ((size_t)b * DMODEL + d) * HW + hw;
    float sv = __ldg(sp + sidx);
    float pv = __ldg(pp + sidx) + __ldg(lvl_emb + lvl * DMODEL + d);
    g_src[idx] = sv;
    g_pos[idx] = pv;
    g_src_h[idx] = __float2half(sv);
    g_q_h[idx]   = __float2half(sv + pv);
}

// ---------------- deformable attention, two-phase (one warp per (b,q,head)) ---------
__global__ __launch_bounds__(256)
void deform_kernel(const __half* __restrict__ value,
                   const float* __restrict__ offaw,
                   __half* __restrict__ out_h)
{
    __shared__ uint4 s_pk[8][16][2];   // [warp][point][tap-pair]

    int gw = (int)((blockIdx.x * blockDim.x + threadIdx.x) >> 5);
    if (gw >= MROWS * NHEADS) return;
    const int lane = threadIdx.x & 31;
    const int wip  = (threadIdx.x >> 5) & 7;
    const int h = gw & 7;
    const int m = gw >> 3;
    const int b = m / L_TOT;
    const int q = m - b * L_TOT;

    // ---- Phase A
    {
        const int pl  = lane & 15;
        const int lvl = pl >> 2;
        float ref_x, ref_y;
        {
            int idx, Wl0;
            if (q < 10000)      { idx = q;         Wl0 = 100; }
            else if (q < 12500) { idx = q - 10000; Wl0 = 50;  }
            else if (q < 13125) { idx = q - 12500; Wl0 = 25;  }
            else                { idx = q - 13125; Wl0 = 13;  }
            int yy = idx / Wl0, xx = idx - yy * Wl0;
            ref_x = (xx + 0.5f) / (float)Wl0;
            ref_y = (yy + 0.5f) / (float)Wl0;
        }
        float logit = __ldg(offaw + (size_t)m * 384 + 256 + h * 16 + pl);
        float e = __expf(logit);
        float ssum = e;
        #pragma unroll
        for (int o = 8; o > 0; o >>= 1) ssum += __shfl_xor_sync(0xFFFFFFFFu, ssum, o);
        float wgt = e / ssum;

        float ox = __ldg(offaw + (size_t)m * 384 + h * 32 + pl * 2);
        float oy = __ldg(offaw + (size_t)m * 384 + h * 32 + pl * 2 + 1);

        const int WlA[4] = {100, 50, 25, 13};
        const int stA[4] = {0, 10000, 12500, 13125};
        const int Wl = WlA[lvl], Hl = WlA[lvl], st = stA[lvl];
        const float fW = (float)Wl, fH = (float)Hl;

        float px = ref_x * fW + ox - 0.5f;
        float py = ref_y * fH + oy - 0.5f;
        float x0f = floorf(px), y0f = floorf(py);
        float wx1 = px - x0f, wy1 = py - y0f;
        int x0 = (int)x0f, y0 = (int)y0f;

        if (lane < 16) {
            uint32_t wb[4], ob[4];
            #pragma unroll
            for (int t = 0; t < 4; t++) {
                int xi = x0 + (t & 1);
                int yi = y0 + (t >> 1);
                bool valid = (xi >= 0) & (xi < Wl) & (yi >= 0) & (yi < Hl);
                int xc = min(max(xi, 0), Wl - 1);
                int yc = min(max(yi, 0), Hl - 1);
                float w = ((t & 1) ? wx1 : 1.f - wx1) * ((t >> 1) ? wy1 : 1.f - wy1)
                          * wgt * (valid ? 1.f : 0.f);
                __half2 wh = __half2half2(__float2half(w));
                wb[t] = *reinterpret_cast<uint32_t*>(&wh);
                ob[t] = (uint32_t)(st + yc * Wl + xc) * 512u;
            }
            s_pk[wip][pl][0] = make_uint4(wb[0], ob[0], wb[1], ob[1]);
            s_pk[wip][pl][1] = make_uint4(wb[2], ob[2], wb[3], ob[3]);
        }
    }
    __syncwarp();

    // ---- Phase B
    const int g4  = lane >> 3;
    const int ch8 = lane & 7;
    const char* vbase = reinterpret_cast<const char*>(value + (size_t)b * L_TOT * 256 + h * 32)
                        + ch8 * 8;
    float4 acc = make_float4(0.f, 0.f, 0.f, 0.f);
    __half2 a0 = __half2half2(__float2half(0.f));
    __half2 a1 = a0;
    #pragma unroll
    for (int pp = 0; pp < 4; pp++) {
        const int pt = pp * 4 + g4;
        const uint4 kA = s_pk[wip][pt][0];
        const uint4 kB = s_pk[wip][pt][1];
        uint2 v;
        v = __ldg(reinterpret_cast<const uint2*>(vbase + kA.y));
        a0 = __hfma2(*reinterpret_cast<const __half2*>(&kA.x), *reinterpret_cast<__half2*>(&v.x), a0);
        a1 = __hfma2(*reinterpret_cast<const __half2*>(&kA.x), *reinterpret_cast<__half2*>(&v.y), a1);
        v = __ldg(reinterpret_cast<const uint2*>(vbase + kA.w));
        a0 = __hfma2(*reinterpret_cast<const __half2*>(&kA.z), *reinterpret_cast<__half2*>(&v.x), a0);
        a1 = __hfma2(*reinterpret_cast<const __half2*>(&kA.z), *reinterpret_cast<__half2*>(&v.y), a1);
        v = __ldg(reinterpret_cast<const uint2*>(vbase + kB.y));
        a0 = __hfma2(*reinterpret_cast<const __half2*>(&kB.x), *reinterpret_cast<__half2*>(&v.x), a0);
        a1 = __hfma2(*reinterpret_cast<const __half2*>(&kB.x), *reinterpret_cast<__half2*>(&v.y), a1);
        v = __ldg(reinterpret_cast<const uint2*>(vbase + kB.w));
        a0 = __hfma2(*reinterpret_cast<const __half2*>(&kB.z), *reinterpret_cast<__half2*>(&v.x), a0);
        a1 = __hfma2(*reinterpret_cast<const __half2*>(&kB.z), *reinterpret_cast<__half2*>(&v.y), a1);
        if (pp & 1) {
            float2 f0 = __half22float2(a0);
            float2 f1 = __half22float2(a1);
            acc.x += f0.x; acc.y += f0.y; acc.z += f1.x; acc.w += f1.y;
            a0 = __half2half2(__float2half(0.f));
            a1 = a0;
        }
    }
    #pragma unroll
    for (int o = 8; o <= 16; o <<= 1) {
        acc.x += __shfl_xor_sync(0xFFFFFFFFu, acc.x, o);
        acc.y += __shfl_xor_sync(0xFFFFFFFFu, acc.y, o);
        acc.z += __shfl_xor_sync(0xFFFFFFFFu, acc.z, o);
        acc.w += __shfl_xor_sync(0xFFFFFFFFu, acc.w, o);
    }
    if (g4 == 0) {
        __half2 h0 = __halves2half2(__float2half(acc.x), __float2half(acc.y));
        __half2 h1 = __halves2half2(__float2half(acc.z), __float2half(acc.w));
        uint2 pkd;
        pkd.x = *reinterpret_cast<uint32_t*>(&h0);
        pkd.y = *reinterpret_cast<uint32_t*>(&h1);
        *reinterpret_cast<uint2*>(out_h + (size_t)m * 256 + h * 32 + ch8 * 4) = pkd;
    }
}

// ---------------- fused residual add + LayerNorm (one warp per row) -----------------
__global__ void add_ln_kernel(const float* __restrict__ X, const __half* __restrict__ R,
                              const float* __restrict__ w, const float* __restrict__ b,
                              const float* __restrict__ pos,
                              float* __restrict__ out,
                              __half* __restrict__ out_h,
                              __half* __restrict__ q_h)
{
    int row = (int)((blockIdx.x * blockDim.x + threadIdx.x) >> 5);
    if (row >= MROWS) return;
    int lane = threadIdx.x & 31;
    const float*  x = X + (size_t)row * DMODEL;
    const __half* r = R + (size_t)row * DMODEL;
    float v[8];
    float s = 0.f;
    #pragma unroll
    for (int j = 0; j < 8; j++) {
        int c = lane + j * 32;
        v[j] = x[c] + __half2float(__ldg(r + c));
        s += v[j];
    }
    #pragma unroll
    for (int o = 16; o > 0; o >>= 1) s += __shfl_xor_sync(0xFFFFFFFFu, s, o);
    float mean = s * (1.f / 256.f);
    float qv = 0.f;
    #pragma unroll
    for (int j = 0; j < 8; j++) { float d = v[j] - mean; qv += d * d; }
    #pragma unroll
    for (int o = 16; o > 0; o >>= 1) qv += __shfl_xor_sync(0xFFFFFFFFu, qv, o);
    float invs = rsqrtf(qv * (1.f / 256.f) + 1e-5f);
    #pragma unroll
    for (int j = 0; j < 8; j++) {
        int c = lane + j * 32;
        float o = (v[j] - mean) * invs * __ldg(w + c) + __ldg(b + c);
        size_t oi = (size_t)row * DMODEL + c;
        out[oi] = o;
        out_h[oi] = __float2half(o);
        if (pos != nullptr) q_h[oi] = __float2half(o + __ldg(pos + oi));
    }
}

// ---------------- tail write: level_start_index as floats at out[MROWS*DMODEL..] ----
__global__ void write_tail_kernel(float* __restrict__ out, int n)
{
    int i = threadIdx.x;
    const long long tot = (long long)MROWS * DMODEL;
    if (tot + i < n) {
        float st = (i == 0) ? 0.f : (i == 1) ? 10000.f : (i == 2) ? 12500.f : 13125.f;
        if (i < 4) out[tot + i] = st;
    }
}

// ---------------- host launch ----------------
extern "C" void kernel_launch(void* const* d_in, const int* in_sizes, int n_in,
                              void* d_out, int out_size)
{
    // setup_inputs() dict order is INTERLEAVED: src0, pos0, src1, pos1, ...
    const float* s0 = (const float*)d_in[0];
    const float* p0 = (const float*)d_in[1];
    const float* s1 = (const float*)d_in[2];
    const float* p1 = (const float*)d_in[3];
    const float* s2 = (const float*)d_in[4];
    const float* p2 = (const float*)d_in[5];
    const float* s3 = (const float*)d_in[6];
    const float* p3 = (const float*)d_in[7];
    const float* lvl_emb = (const float*)d_in[8];
    const float* so_w = (const float*)d_in[9];
    const float* so_b = (const float*)d_in[10];
    const float* aw_w = (const float*)d_in[11];
    const float* aw_b = (const float*)d_in[12];
    const float* vp_w = (const float*)d_in[13];
    const float* vp_b = (const float*)d_in[14];
    const float* op_w = (const float*)d_in[15];
    const float* op_b = (const float*)d_in[16];
    const float* n1_w = (const float*)d_in[17];
    const float* n1_b = (const float*)d_in[18];
    const float* f1_w = (const float*)d_in[19];
    const float* f1_b = (const float*)d_in[20];
    const float* f2_w = (const float*)d_in[21];
    const float* f2_b = (const float*)d_in[22];
    const float* n2_w = (const float*)d_in[23];
    const float* n2_b = (const float*)d_in[24];

    float *pg_src, *pg_pos, *pg_offaw;
    __half *pg_tmp_h, *pg_val_h, *pg_src_h, *pg_q_h, *pg_attn_h, *pg_h_h, *pg_w;
    cudaGetSymbolAddress((void**)&pg_src,   g_src);
    cudaGetSymbolAddress((void**)&pg_pos,   g_pos);
    cudaGetSymbolAddress((void**)&pg_offaw, g_offaw);
    cudaGetSymbolAddress((void**)&pg_tmp_h, g_tmp_h);
    cudaGetSymbolAddress((void**)&pg_val_h, g_val_h);
    cudaGetSymbolAddress((void**)&pg_src_h, g_src_h);
    cudaGetSymbolAddress((void**)&pg_q_h,   g_q_h);
    cudaGetSymbolAddress((void**)&pg_attn_h, g_attn_h);
    cudaGetSymbolAddress((void**)&pg_h_h,   g_h_h);
    cudaGetSymbolAddress((void**)&pg_w,     g_w);

    // dynamic smem: 2 stages x 55296 B
    const int GEMM_SMEM = 110592;
    cudaFuncSetAttribute(mma_gemm<false, 0>, cudaFuncAttributeMaxDynamicSharedMemorySize, GEMM_SMEM);
    cudaFuncSetAttribute(mma_gemm<false, 1>, cudaFuncAttributeMaxDynamicSharedMemorySize, GEMM_SMEM);
    cudaFuncSetAttribute(mma_gemm<true, 1>,  cudaFuncAttributeMaxDynamicSharedMemorySize, GEMM_SMEM);
    cudaFuncSetAttribute(dual_gemm,          cudaFuncAttributeMaxDynamicSharedMemorySize, GEMM_SMEM);

    const long long totElem = (long long)MROWS * DMODEL;
    const int ew_grid = (int)((totElem + 255) / 256);

    wprep_all_kernel<<<(NLAYERS_C * LW_STRIDE + 255) / 256, 256>>>(
        vp_w, so_w, aw_w, op_w, f1_w, f2_w, pg_w);
    flatten_kernel<<<ew_grid, 256>>>(s0, s1, s2, s3, p0, p1, p2, p3, lvl_emb);

    const int mblk = (MROWS + 255) / 256;   // 208
    const dim3 blk(512);
    const int ln_grid = (MROWS * 32 + 255) / 256;
    const int deform_grid = (MROWS * NHEADS * 32 + 255) / 256;

    for (int i = 0; i < NLAYERS_C; i++) {
        size_t wb = (size_t)i * LW_STRIDE;
        const __half* vp_h = pg_w + wb + OFF_VP;
        const __half* sa_h = pg_w + wb + OFF_SOAW;
        const __half* op_h = pg_w + wb + OFF_OP;
        const __half* f1_h = pg_w + wb + OFF_F1;
        const __half* f2_h = pg_w + wb + OFF_F2;
        const bool last = (i == NLAYERS_C - 1);

        // fused launch: value = src @ vp_w (fp16 out) || offaw = q @ soaw_w (fp32 out)
        dual_gemm<<<dim3(mblk, 5), blk, GEMM_SMEM>>>(
            pg_src_h, vp_h, vp_b + (size_t)i * 256, pg_val_h, 256, 2,
            pg_q_h, sa_h, so_b + (size_t)i * 256, aw_b + (size_t)i * 128,
            pg_offaw, 384, MROWS, 256);
        // deformable sampling -> attn fp16
        deform_kernel<<<deform_grid, 256>>>(pg_val_h, pg_offaw, pg_attn_h);
        // output proj (fp16 increment out)
        mma_gemm<false, 1><<<dim3(mblk, 2), blk, GEMM_SMEM>>>(
            pg_attn_h, op_h, op_b + (size_t)i * 256, op_b + (size_t)i * 256, 256,
            nullptr, pg_tmp_h, MROWS, 256, 256);
        // src = LN(src + attn_proj)
        add_ln_kernel<<<ln_grid, 256>>>(pg_src, pg_tmp_h,
                                        n1_w + (size_t)i * DMODEL, n1_b + (size_t)i * DMODEL,
                                        nullptr, pg_src, pg_src_h, nullptr);
        // h = relu(src @ f1_w + f1_b)  (fp16 out)
        mma_gemm<true, 1><<<dim3(mblk, 8), blk, GEMM_SMEM>>>(
            pg_src_h, f1_h, f1_b + (size_t)i * DFFN, f1_b + (size_t)i * DFFN, DFFN,
            nullptr, pg_h_h, MROWS, 256, DFFN);
        // tmp = h @ f2_w + f2_b  (fp16 increment out)
        mma_gemm<false, 1><<<dim3(mblk, 2), blk, GEMM_SMEM>>>(
            pg_h_h, f2_h, f2_b + (size_t)i * 256, f2_b + (size_t)i * 256, 256,
            nullptr, pg_tmp_h, MROWS, 1024, 256);
        // src = LN(src + ffn); last layer writes fp32 directly into d_out
        add_ln_kernel<<<ln_grid, 256>>>(pg_src, pg_tmp_h,
                                        n2_w + (size_t)i * DMODEL, n2_b + (size_t)i * DMODEL,
                                        last ? nullptr : pg_pos,
                                        last ? (float*)d_out : pg_src,
                                        pg_src_h,
                                        last ? nullptr : pg_q_h);
    }

    write_tail_kernel<<<1, 32>>>((float*)d_out, out_size);
}